// round 1
// baseline (speedup 1.0000x reference)
#include <cuda_runtime.h>
#include <cstdint>

#define HH 128
#define TT 512
#define BB 220
#define NROWS 660
#define NCLUSTER 66
#define RPC 10               // rows per cluster
#define NBLOCKS (NCLUSTER*2)
#define NTHREADS 256
#define PITCH 132            // floats per W row in smem (16B aligned, conflict-free)
#define RPT 5                // rows per thread

typedef unsigned long long u64t;

// 660 * 512 * 128 floats = 173 MB scratch for all LSTM outputs
__device__ float g_hout[(size_t)NROWS * TT * HH];

__device__ __forceinline__ u64t ffma2(u64t a, u64t b, u64t c) {
  u64t d;
  asm("fma.rn.f32x2 %0, %1, %2, %3;" : "=l"(d) : "l"(a), "l"(b), "l"(c));
  return d;
}
__device__ __forceinline__ u64t fadd2(u64t a, u64t b) {
  u64t d;
  asm("add.rn.f32x2 %0, %1, %2;" : "=l"(d) : "l"(a), "l"(b));
  return d;
}
__device__ __forceinline__ void unpack2(u64t v, float &lo, float &hi) {
  asm("mov.b64 {%0, %1}, %2;" : "=f"(lo), "=f"(hi) : "l"(v));
}
__device__ __forceinline__ float sigm(float x) {
  return __fdividef(1.f, 1.f + __expf(-x));
}
__device__ __forceinline__ float tanh_f(float x) {
  // robust: x->+inf => 2/1-1=1 ; x->-inf => 2/inf-1=-1
  return __fdividef(2.f, 1.f + __expf(-2.f * x)) - 1.f;
}

// shared memory layout (in floats)
#define SM_W 0
#define SM_H (256*PITCH)                 // 2 buffers * RPC rows * HH
#define SM_X (SM_H + 2*RPC*HH)           // RPC rows * TT * 2
#define SM_FLOATS (SM_X + RPC*TT*2)
#define SM_BYTES (SM_FLOATS*4 + 128*4*RPT*8)   // + exchange buffer (u64 per acc)

extern __shared__ float smem_f[];

__global__ void __cluster_dims__(2,1,1) __launch_bounds__(NTHREADS, 1)
lstm_kernel(const float* __restrict__ x0p, const float* __restrict__ x1p,
            const float* __restrict__ x2p,
            const float* __restrict__ W_ih, const float* __restrict__ W_hh,
            const float* __restrict__ b_ih, const float* __restrict__ b_hh)
{
  float* W_sm = smem_f + SM_W;
  float* h_sm = smem_f + SM_H;
  float* x_sm = smem_f + SM_X;
  u64t*  ex   = (u64t*)(smem_f + SM_FLOATS);

  const int tid = threadIdx.x;
  unsigned rank;
  asm("mov.u32 %0, %%cluster_ctarank;" : "=r"(rank));
  const int cid  = blockIdx.x >> 1;
  const int row0 = cid * RPC;

  // ---- preload this block's 256 W_hh rows (its j-half of all 4 gates) ----
  for (int idx = tid; idx < 256*32; idx += NTHREADS) {
    int gl = idx >> 5, k4 = idx & 31;
    int gt = gl >> 6, qq = gl & 63;
    int grow = gt*128 + (int)rank*64 + qq;
    float4 v = *(const float4*)(W_hh + (size_t)grow*HH + k4*4);
    *(float4*)(W_sm + gl*PITCH + k4*4) = v;
  }
  // ---- preload x (first 2 of 4 coords) for all T steps of our 10 rows ----
  for (int idx = tid; idx < RPC*TT; idx += NTHREADS) {
    int r = idx >> 9, t = idx & (TT-1);
    int row = row0 + r;
    const float* xp; int b;
    if (row < BB)        { xp = x0p; b = row; }
    else if (row < 2*BB) { xp = x1p; b = row - BB; }
    else                 { xp = x2p; b = row - 2*BB; }
    float4 v = *(const float4*)(xp + ((size_t)b*TT + t)*4);
    x_sm[(r*TT + t)*2]     = v.x;
    x_sm[(r*TT + t)*2 + 1] = v.y;
  }
  // zero h buffer 0
  for (int i = tid; i < RPC*HH; i += NTHREADS) h_sm[i] = 0.f;
  __syncthreads();
  asm volatile("barrier.cluster.arrive.aligned;" ::: "memory");
  asm volatile("barrier.cluster.wait.aligned;"   ::: "memory");

  const int q  = tid & 63;          // local j index
  const int rg = (tid >> 6) & 1;    // row-group (rows rg*5 .. rg*5+4)
  const int kh = tid >> 7;          // k-half
  const int jg = (int)rank*64 + q;  // global h index this thread owns

  float biasr[4], wi0[4], wi1[4];
  if (kh == 0) {
    #pragma unroll
    for (int g = 0; g < 4; ++g) {
      int grow = g*128 + jg;
      biasr[g] = b_ih[grow] + b_hh[grow];
      wi0[g]   = W_ih[grow*2];
      wi1[g]   = W_ih[grow*2 + 1];
    }
  }
  float c_state[RPT];
  #pragma unroll
  for (int r = 0; r < RPT; ++r) c_state[r] = 0.f;

  const float* wbase = W_sm + q*PITCH + kh*64;
  const int exslot = (rg*64 + q) * (4*RPT);

  int cur = 0;
  for (int t = 0; t < TT; ++t) {
    u64t acc[4][RPT];
    #pragma unroll
    for (int g = 0; g < 4; ++g)
      #pragma unroll
      for (int r = 0; r < RPT; ++r) acc[g][r] = 0ull;

    const float* hbase = h_sm + cur*(RPC*HH) + rg*(RPT*HH) + kh*64;

    #pragma unroll 4
    for (int k = 0; k < 64; k += 4) {
      ulonglong2 wv[4];
      #pragma unroll
      for (int g = 0; g < 4; ++g)
        wv[g] = *(const ulonglong2*)(wbase + g*(64*PITCH) + k);
      ulonglong2 hv[RPT];
      #pragma unroll
      for (int r = 0; r < RPT; ++r)
        hv[r] = *(const ulonglong2*)(hbase + r*HH + k);
      #pragma unroll
      for (int g = 0; g < 4; ++g)
        #pragma unroll
        for (int r = 0; r < RPT; ++r) {
          acc[g][r] = ffma2(wv[g].x, hv[r].x, acc[g][r]);
          acc[g][r] = ffma2(wv[g].y, hv[r].y, acc[g][r]);
        }
    }

    if (kh == 1) {
      #pragma unroll
      for (int g = 0; g < 4; ++g)
        #pragma unroll
        for (int r = 0; r < RPT; ++r)
          ex[exslot + g*RPT + r] = acc[g][r];
    }
    __syncthreads();

    if (kh == 0) {
      #pragma unroll
      for (int r = 0; r < RPT; ++r) {
        int rrow = rg*RPT + r;
        float xv0 = x_sm[(rrow*TT + t)*2];
        float xv1 = x_sm[(rrow*TT + t)*2 + 1];
        float gv[4];
        #pragma unroll
        for (int g = 0; g < 4; ++g) {
          u64t v = fadd2(acc[g][r], ex[exslot + g*RPT + r]);
          float lo, hi; unpack2(v, lo, hi);
          gv[g] = lo + hi + biasr[g] + wi0[g]*xv0 + wi1[g]*xv1;
        }
        float ig = sigm(gv[0]);
        float fg = sigm(gv[1]);
        float gg = tanh_f(gv[2]);
        float og = sigm(gv[3]);
        float c  = fg * c_state[r] + ig * gg;
        c_state[r] = c;
        float h  = og * tanh_f(c);

        int dst = (cur ^ 1)*(RPC*HH) + rrow*HH + jg;
        h_sm[dst] = h;
        unsigned laddr = (unsigned)__cvta_generic_to_shared(h_sm + dst);
        unsigned raddr;
        asm("mapa.shared::cluster.u32 %0, %1, %2;" : "=r"(raddr)
            : "r"(laddr), "r"(rank ^ 1u));
        asm volatile("st.shared::cluster.f32 [%0], %1;"
                     :: "r"(raddr), "f"(h) : "memory");
        g_hout[((size_t)(row0 + rrow)*TT + t)*HH + jg] = h;
      }
    }
    asm volatile("barrier.cluster.arrive.aligned;" ::: "memory");
    asm volatile("barrier.cluster.wait.aligned;"   ::: "memory");
    cur ^= 1;
  }
}

// ---------------- distance / gather kernel ----------------
__global__ void dist_kernel(const int* __restrict__ Lt, const int* __restrict__ La,
                            const int* __restrict__ Lf,
                            const int* __restrict__ tasl, const int* __restrict__ tfsl,
                            const int* __restrict__ asl,  const int* __restrict__ fsl,
                            float* __restrict__ out)
{
  int g = (blockIdx.x * blockDim.x + threadIdx.x) >> 5;
  int lane = threadIdx.x & 31;
  if (g >= 4840) return;
  int rowA, tA, rowB, tB;
  if (g < 220)       { int b = g;       rowA = b;  tA = max(Lt[b]-1, 0);   rowB = 220+b; tB = max(La[b]-1, 0); }
  else if (g < 440)  { int b = g-220;   rowA = b;  tA = max(Lt[b]-1, 0);   rowB = 440+b; tB = max(Lf[b]-1, 0); }
  else if (g < 2640) { int k = g-440;   int b = k/10; rowA = b; tA = max(tasl[k]-1, 0); rowB = 220+b; tB = max(asl[k]-1, 0); }
  else               { int k = g-2640;  int b = k/10; rowA = b; tA = max(tfsl[k]-1, 0); rowB = 440+b; tB = max(fsl[k]-1, 0); }

  const float4* pa = (const float4*)(g_hout + ((size_t)rowA*TT + tA)*HH);
  const float4* pb = (const float4*)(g_hout + ((size_t)rowB*TT + tB)*HH);
  float4 a = pa[lane], b4 = pb[lane];
  float dx = a.x-b4.x, dy = a.y-b4.y, dz = a.z-b4.z, dw = a.w-b4.w;
  float s = dx*dx + dy*dy + dz*dz + dw*dw;
  #pragma unroll
  for (int off = 16; off; off >>= 1) s += __shfl_xor_sync(0xffffffffu, s, off);
  if (lane == 0) out[g] = __expf(-__fsqrt_rn(s));
}

extern "C" void kernel_launch(void* const* d_in, const int* in_sizes, int n_in,
                              void* d_out, int out_size)
{
  const float* traj = (const float*)d_in[0];
  const int*   Lt   = (const int*)  d_in[1];
  const int*   tasl = (const int*)  d_in[2];
  const int*   tfsl = (const int*)  d_in[3];
  const float* anch = (const float*)d_in[4];
  const int*   La   = (const int*)  d_in[5];
  const int*   asl  = (const int*)  d_in[6];
  const float* fare = (const float*)d_in[7];
  const int*   Lf   = (const int*)  d_in[8];
  const int*   fsl  = (const int*)  d_in[9];
  const float* W_ih = (const float*)d_in[10];
  const float* W_hh = (const float*)d_in[11];
  const float* b_ih = (const float*)d_in[12];
  const float* b_hh = (const float*)d_in[13];

  cudaFuncSetAttribute(lstm_kernel, cudaFuncAttributeMaxDynamicSharedMemorySize,
                       SM_BYTES);
  lstm_kernel<<<NBLOCKS, NTHREADS, SM_BYTES>>>(traj, anch, fare, W_ih, W_hh,
                                               b_ih, b_hh);
  dist_kernel<<<(4840*32 + 255)/256, 256>>>(Lt, La, Lf, tasl, tfsl, asl, fsl,
                                            (float*)d_out);
}

// round 2
// speedup vs baseline: 1.3229x; 1.3229x over previous
#include <cuda_runtime.h>
#include <cstdint>

#define HH 128
#define TT 512
#define BB 220
#define NROWS 660
#define NCLUSTER 66
#define RPC 10
#define NBLOCKS (NCLUSTER*2)
#define NTHREADS 256

typedef unsigned long long u64t;

// 660 * 512 * 128 floats = 173 MB scratch for all LSTM outputs
__device__ float g_hout[(size_t)NROWS * TT * HH];

__device__ __forceinline__ u64t ffma2(u64t a, u64t b, u64t c) {
  u64t d;
  asm("fma.rn.f32x2 %0, %1, %2, %3;" : "=l"(d) : "l"(a), "l"(b), "l"(c));
  return d;
}
__device__ __forceinline__ void unpack2(u64t v, float &lo, float &hi) {
  asm("mov.b64 {%0, %1}, %2;" : "=f"(lo), "=f"(hi) : "l"(v));
}
__device__ __forceinline__ float sigm(float x) {
  return __fdividef(1.f, 1.f + __expf(-x));
}
__device__ __forceinline__ float tanh_f(float x) {
  return __fdividef(2.f, 1.f + __expf(-2.f * x)) - 1.f;
}

// shared memory layout (float offsets)
#define SM_H  0                       // 2 * 10 * 128 = 2560
#define SM_X  2560                    // 10 * 512 * 2 = 10240
#define SM_EX 12800                   // 4kh * 4g * 10r * 64q = 10240
#define SM_FLOATS 23040
#define SM_BYTES (SM_FLOATS*4)

extern __shared__ float smem_f[];

__global__ void __cluster_dims__(2,1,1) __launch_bounds__(NTHREADS, 1)
lstm_kernel(const float* __restrict__ x0p, const float* __restrict__ x1p,
            const float* __restrict__ x2p,
            const float* __restrict__ W_ih, const float* __restrict__ W_hh,
            const float* __restrict__ b_ih, const float* __restrict__ b_hh)
{
  float* h_sm = smem_f + SM_H;
  float* x_sm = smem_f + SM_X;
  float* ex   = smem_f + SM_EX;

  const int tid = threadIdx.x;
  unsigned rank;
  asm("mov.u32 %0, %%cluster_ctarank;" : "=r"(rank));
  const int cid  = blockIdx.x >> 1;
  const int row0 = cid * RPC;

  const int q  = tid & 63;          // j lane
  const int kh = tid >> 6;          // k quarter 0..3
  const int jg = (int)rank*64 + q;  // global hidden index this thread owns

  // ---- W_hh resident in registers: 4 gates x 32 k (= this thread's quarter) ----
  u64t wreg[4][16];
  #pragma unroll
  for (int g = 0; g < 4; ++g) {
    const ulonglong2* wp =
        (const ulonglong2*)(W_hh + (size_t)(g*128 + jg)*HH + kh*32);
    #pragma unroll
    for (int i = 0; i < 8; ++i) {
      ulonglong2 v = wp[i];
      wreg[g][2*i]   = v.x;
      wreg[g][2*i+1] = v.y;
    }
  }

  // ---- preload x (first 2 of 4 coords) for all T steps of our 10 rows ----
  for (int idx = tid; idx < RPC*TT; idx += NTHREADS) {
    int r = idx >> 9, t = idx & (TT-1);
    int row = row0 + r;
    const float* xp; int b;
    if (row < BB)        { xp = x0p; b = row; }
    else if (row < 2*BB) { xp = x1p; b = row - BB; }
    else                 { xp = x2p; b = row - 2*BB; }
    float4 v = *(const float4*)(xp + ((size_t)b*TT + t)*4);
    x_sm[(r*TT + t)*2]     = v.x;
    x_sm[(r*TT + t)*2 + 1] = v.y;
  }
  // zero h buffer 0
  for (int i = tid; i < RPC*HH; i += NTHREADS) h_sm[i] = 0.f;

  // ---- epilogue-thread constants (threads 0..127, one row-half each) ----
  const int rh = (tid >> 6) & 1;
  float biasr[4], wi0[4], wi1[4], c_state[5], hval[5];
  if (tid < 128) {
    #pragma unroll
    for (int g = 0; g < 4; ++g) {
      int grow = g*128 + jg;
      biasr[g] = b_ih[grow] + b_hh[grow];
      wi0[g]   = W_ih[grow*2];
      wi1[g]   = W_ih[grow*2 + 1];
    }
    #pragma unroll
    for (int r = 0; r < 5; ++r) c_state[r] = 0.f;
  }
  __syncthreads();
  asm volatile("barrier.cluster.arrive.aligned;" ::: "memory");

  int cur = 0;
  for (int t = 0; t < TT; ++t) {
    asm volatile("barrier.cluster.wait.aligned;" ::: "memory");

    // ---- partial gate sums: this thread's k-quarter, all 4 gates, 10 rows ----
    #pragma unroll
    for (int p = 0; p < 2; ++p) {          // two passes of 5 rows (reg pressure)
      u64t acc[4][5];
      #pragma unroll
      for (int g = 0; g < 4; ++g)
        #pragma unroll
        for (int r = 0; r < 5; ++r) acc[g][r] = 0ull;

      const float* hb = h_sm + cur*(RPC*HH) + p*(5*HH) + kh*32;
      #pragma unroll
      for (int r = 0; r < 5; ++r) {
        ulonglong2 hv[8];
        #pragma unroll
        for (int i = 0; i < 8; ++i)
          hv[i] = *(const ulonglong2*)(hb + r*HH + i*4);
        #pragma unroll
        for (int g = 0; g < 4; ++g) {
          #pragma unroll
          for (int i = 0; i < 8; ++i) {
            acc[g][r] = ffma2(wreg[g][2*i],   hv[i].x, acc[g][r]);
            acc[g][r] = ffma2(wreg[g][2*i+1], hv[i].y, acc[g][r]);
          }
        }
      }
      // horizontal reduce to fp32 and publish partials
      #pragma unroll
      for (int g = 0; g < 4; ++g)
        #pragma unroll
        for (int r = 0; r < 5; ++r) {
          float lo, hi; unpack2(acc[g][r], lo, hi);
          ex[((kh*4 + g)*10 + p*5 + r)*64 + q] = lo + hi;
        }
    }
    __syncthreads();

    // ---- epilogue: combine 4 k-quarters, activations, h writes ----
    if (tid < 128) {
      int nxt = cur ^ 1;
      #pragma unroll
      for (int r = 0; r < 5; ++r) {
        int rr = rh*5 + r;
        float x0 = x_sm[(rr*TT + t)*2];
        float x1 = x_sm[(rr*TT + t)*2 + 1];
        float gv[4];
        #pragma unroll
        for (int g = 0; g < 4; ++g) {
          float s = ex[(( 0 + g)*10 + rr)*64 + q]
                  + ex[(( 4 + g)*10 + rr)*64 + q]
                  + ex[(( 8 + g)*10 + rr)*64 + q]
                  + ex[((12 + g)*10 + rr)*64 + q];
          gv[g] = s + biasr[g] + wi0[g]*x0 + wi1[g]*x1;
        }
        float ig = sigm(gv[0]);
        float fg = sigm(gv[1]);
        float gg = tanh_f(gv[2]);
        float og = sigm(gv[3]);
        float c  = fg * c_state[r] + ig * gg;
        c_state[r] = c;
        float h  = og * tanh_f(c);
        hval[r] = h;

        int dst = nxt*(RPC*HH) + rr*HH + jg;
        h_sm[dst] = h;
        unsigned laddr = (unsigned)__cvta_generic_to_shared(h_sm + dst);
        unsigned raddr;
        asm("mapa.shared::cluster.u32 %0, %1, %2;" : "=r"(raddr)
            : "r"(laddr), "r"(rank ^ 1u));
        asm volatile("st.shared::cluster.f32 [%0], %1;"
                     :: "r"(raddr), "f"(h) : "memory");
      }
    }
    asm volatile("barrier.cluster.arrive.aligned;" ::: "memory");

    // global h stores overlap the peer's barrier wait
    if (tid < 128) {
      #pragma unroll
      for (int r = 0; r < 5; ++r)
        g_hout[((size_t)(row0 + rh*5 + r)*TT + t)*HH + jg] = hval[r];
    }
    cur ^= 1;
  }
  asm volatile("barrier.cluster.wait.aligned;" ::: "memory");
}

// ---------------- distance / gather kernel ----------------
__global__ void dist_kernel(const int* __restrict__ Lt, const int* __restrict__ La,
                            const int* __restrict__ Lf,
                            const int* __restrict__ tasl, const int* __restrict__ tfsl,
                            const int* __restrict__ asl,  const int* __restrict__ fsl,
                            float* __restrict__ out)
{
  int g = (blockIdx.x * blockDim.x + threadIdx.x) >> 5;
  int lane = threadIdx.x & 31;
  if (g >= 4840) return;
  int rowA, tA, rowB, tB;
  if (g < 220)       { int b = g;       rowA = b;  tA = max(Lt[b]-1, 0);   rowB = 220+b; tB = max(La[b]-1, 0); }
  else if (g < 440)  { int b = g-220;   rowA = b;  tA = max(Lt[b]-1, 0);   rowB = 440+b; tB = max(Lf[b]-1, 0); }
  else if (g < 2640) { int k = g-440;   int b = k/10; rowA = b; tA = max(tasl[k]-1, 0); rowB = 220+b; tB = max(asl[k]-1, 0); }
  else               { int k = g-2640;  int b = k/10; rowA = b; tA = max(tfsl[k]-1, 0); rowB = 440+b; tB = max(fsl[k]-1, 0); }

  const float4* pa = (const float4*)(g_hout + ((size_t)rowA*TT + tA)*HH);
  const float4* pb = (const float4*)(g_hout + ((size_t)rowB*TT + tB)*HH);
  float4 a = pa[lane], b4 = pb[lane];
  float dx = a.x-b4.x, dy = a.y-b4.y, dz = a.z-b4.z, dw = a.w-b4.w;
  float s = dx*dx + dy*dy + dz*dz + dw*dw;
  #pragma unroll
  for (int off = 16; off; off >>= 1) s += __shfl_xor_sync(0xffffffffu, s, off);
  if (lane == 0) out[g] = __expf(-__fsqrt_rn(s));
}

extern "C" void kernel_launch(void* const* d_in, const int* in_sizes, int n_in,
                              void* d_out, int out_size)
{
  const float* traj = (const float*)d_in[0];
  const int*   Lt   = (const int*)  d_in[1];
  const int*   tasl = (const int*)  d_in[2];
  const int*   tfsl = (const int*)  d_in[3];
  const float* anch = (const float*)d_in[4];
  const int*   La   = (const int*)  d_in[5];
  const int*   asl  = (const int*)  d_in[6];
  const float* fare = (const float*)d_in[7];
  const int*   Lf   = (const int*)  d_in[8];
  const int*   fsl  = (const int*)  d_in[9];
  const float* W_ih = (const float*)d_in[10];
  const float* W_hh = (const float*)d_in[11];
  const float* b_ih = (const float*)d_in[12];
  const float* b_hh = (const float*)d_in[13];

  cudaFuncSetAttribute(lstm_kernel, cudaFuncAttributeMaxDynamicSharedMemorySize,
                       SM_BYTES);
  lstm_kernel<<<NBLOCKS, NTHREADS, SM_BYTES>>>(traj, anch, fare, W_ih, W_hh,
                                               b_ih, b_hh);
  dist_kernel<<<(4840*32 + 255)/256, 256>>>(Lt, La, Lf, tasl, tfsl, asl, fsl,
                                            (float*)d_out);
}